// round 17
// baseline (speedup 1.0000x reference)
#include <cuda_runtime.h>
#include <stdint.h>

#define NPRED    25200
#define PRED_C   9
#define TOPK     1000
#define CONF_T   0.7f
#define IOU_T    0.45f
#define MASKW    32
#define BMAX     32

#define NSLICE   25
#define ROWS_SL  1008
#define FILT_T   256
#define SLICE_F4 2268          // 1008*9/4 float4s per slice

#define CANDCAP  4096
#define SEL_N    1024
#define SORT_T   1024

#define MSLICES  16
#define MASK_T   256
#define NWARPS_M (MSLICES * (MASK_T / 32))    // 128 warps per image
#define TASKS    16872                        // sum_w min(1000, 32w+32)

#define SWEEP_T  1024
#define NGROUPS  4

typedef unsigned long long u64;
typedef unsigned int u32;

// ---------------- global scratch ----------------
__device__ int    g_cnt [BMAX * NSLICE];
__device__ u64    g_cand[BMAX * NSLICE * ROWS_SL];
__device__ float4 g_box [BMAX * 1024];
__device__ float  g_score[BMAX * 1024];
__device__ float  g_area[BMAX * 1024];
__device__ int    g_idx [BMAX * 1024];
// transposed mask: g_maskT[img][w*1024 + i] = suppression word w of row i.
__device__ u32    g_maskT[BMAX * 32 * 1024];

// ============================================================
// 1) filter: coalesced float4 staging via smem
// ============================================================
__global__ __launch_bounds__(FILT_T)
void k_filter(const float* __restrict__ pred, int img_base)
{
    __shared__ float sdata[ROWS_SL * PRED_C];
    __shared__ u64 buf[ROWS_SL];
    __shared__ int cnt;

    const int img   = img_base + blockIdx.x;
    const int slice = blockIdx.y;
    const int tid   = threadIdx.x;

    if (tid == 0) cnt = 0;

    {
        const float4* src = (const float4*)(pred +
            (size_t)img * NPRED * PRED_C + (size_t)slice * ROWS_SL * PRED_C);
        float4* dst = (float4*)sdata;
        #pragma unroll
        for (int r = 0; r < 9; r++) {
            int k = tid + r * FILT_T;
            if (k < SLICE_F4) dst[k] = src[k];
        }
    }
    __syncthreads();

    const int base = slice * ROWS_SL;
    #pragma unroll
    for (int r = 0; r < 4; r++) {
        int row = tid + r * FILT_T;
        if (row < ROWS_SL) {
            float obj = sdata[row * PRED_C + 4];
            float cls = sdata[row * PRED_C + 5];
            float conf = __fmul_rn(obj, cls);
            if (obj > CONF_T && conf > CONF_T) {
                int i = base + row;
                int pos = atomicAdd(&cnt, 1);
                buf[pos] = ((u64)__float_as_uint(conf) << 32) |
                           (u64)(0xFFFFFFFFu - (u32)i);
            }
        }
    }
    __syncthreads();

    int n = cnt;
    if (tid == 0) g_cnt[img * NSLICE + slice] = n;
    u64* dst = g_cand + (size_t)(img * NSLICE + slice) * ROWS_SL;
    for (int k = tid; k < n; k += FILT_T) dst[k] = buf[k];
}

// ============================================================
// 2) sort (R16 verbatim + img_base)
// ============================================================
__global__ __launch_bounds__(SORT_T, 1)
void k_sort(const float* __restrict__ pred, int img_base)
{
    extern __shared__ unsigned char sraw[];
    u64* skey  = (u64*)sraw;
    u64* skey2 = skey + CANDCAP;
    u64* skey3 = skey2 + SEL_N;
    u32* hist  = (u32*)(skey3 + SEL_N);
    u32* wsum  = hist + 1024;
    u32* woff  = wsum + 32;
    int* spfx  = (int*)(woff + 32);
    int* misc  = spfx + 33;

    const int img = img_base + blockIdx.x;
    const int tid = threadIdx.x;
    const int lane = tid & 31, warp = tid >> 5;
    const float* p = pred + (size_t)img * NPRED * PRED_C;

    if (tid < 32) {
        int c = (tid < NSLICE) ? g_cnt[img * NSLICE + tid] : 0;
        int x = c;
        #pragma unroll
        for (int d = 1; d < 32; d <<= 1) {
            int y = __shfl_up_sync(0xFFFFFFFFu, x, d);
            if ((tid & 31) >= d) x += y;
        }
        spfx[tid + 1] = x;
        if (tid == 0) spfx[0] = 0;
        if (tid == 31) misc[0] = x;
    }
    __syncthreads();

    int total = misc[0];
    if (total > CANDCAP) total = CANDCAP;

    for (int k = tid; k < total; k += SORT_T) {
        int lo = 0, hi = NSLICE;
        #pragma unroll
        for (int it = 0; it < 5; it++) {
            int mid = (lo + hi) >> 1;
            if (spfx[mid] <= k) lo = mid; else hi = mid;
        }
        skey[k] = g_cand[(size_t)(img * NSLICE + lo) * ROWS_SL + (k - spfx[lo])];
    }
    for (int k = total + tid; k < CANDCAP; k += SORT_T) skey[k] = 0ull;
    hist[tid] = 0;
    __syncthreads();

    for (int k = tid; k < total; k += SORT_T) {
        u32 bits = (u32)(skey[k] >> 32);
        int b = (int)((bits - 0x3F000000u) >> 13);
        b = b < 0 ? 0 : (b > 1023 ? 1023 : b);
        atomicAdd(&hist[b], 1u);
    }
    __syncthreads();

    {
        u32 x = hist[tid];
        #pragma unroll
        for (int d = 1; d < 32; d <<= 1) {
            u32 y = __shfl_down_sync(0xFFFFFFFFu, x, d);
            if (lane + d < 32) x += y;
        }
        if (lane == 0) wsum[warp] = x;
        __syncthreads();
        if (warp == 0) {
            u32 t = wsum[lane];
            u32 sx = t;
            #pragma unroll
            for (int d = 1; d < 32; d <<= 1) {
                u32 y = __shfl_down_sync(0xFFFFFFFFu, sx, d);
                if (lane + d < 32) sx += y;
            }
            woff[lane] = sx - t;
        }
        __syncthreads();
        hist[tid] = x + woff[warp];
        __syncthreads();
    }

    int need = total < TOPK ? total : TOPK;
    if ((int)hist[tid] >= need && (tid == 1023 || (int)hist[tid + 1] < need))
        misc[1] = tid;
    if (tid == 0) misc[2] = 0;
    __syncthreads();

    int T = misc[1];
    int kept = (int)hist[T];
    bool fallback = (kept > SEL_N);

    u64 mykey;
    if (!fallback) {
        for (int k = tid; k < CANDCAP; k += SORT_T) {
            bool take = false;
            u64 key = 0ull;
            if (k < total) {
                key = skey[k];
                u32 bits = (u32)(key >> 32);
                int b = (int)((bits - 0x3F000000u) >> 13);
                b = b < 0 ? 0 : (b > 1023 ? 1023 : b);
                take = (b >= T);
            }
            u32 bal = __ballot_sync(0xFFFFFFFFu, take);
            if (bal) {
                int nset = __popc(bal);
                int base_pos;
                if (lane == __ffs(bal) - 1)
                    base_pos = atomicAdd(&misc[2], nset);
                base_pos = __shfl_sync(0xFFFFFFFFu, base_pos, __ffs(bal) - 1);
                if (take) {
                    int off = __popc(bal & ((1u << lane) - 1u));
                    skey2[base_pos + off] = key;
                }
            }
        }
        __syncthreads();
        for (int k = kept + tid; k < SEL_N; k += SORT_T) skey2[k] = 0ull;
        __syncthreads();

        u64 v = skey2[tid];
        #pragma unroll
        for (int k = 2; k <= 32; k <<= 1) {
            #pragma unroll
            for (int j = k >> 1; j > 0; j >>= 1) {
                u64 o = __shfl_xor_sync(0xFFFFFFFFu, v, j);
                bool keep_max = ((tid & j) == 0) == ((tid & k) == 0);
                bool vbig = v > o;
                v = (keep_max == vbig) ? v : o;
            }
        }
        u64* bufs[2] = { skey2, skey3 };
        int cur = 0;
        bufs[cur][tid] = v;
        __syncthreads();
        #pragma unroll
        for (int k = 64; k <= SEL_N; k <<= 1) {
            for (int j = k >> 1; j >= 32; j >>= 1) {
                u64 o = bufs[cur][tid ^ j];
                bool keep_max = ((tid & j) == 0) == ((tid & k) == 0);
                bool vbig = v > o;
                v = (keep_max == vbig) ? v : o;
                bufs[cur ^ 1][tid] = v;
                cur ^= 1;
                __syncthreads();
            }
            #pragma unroll
            for (int j = 16; j > 0; j >>= 1) {
                u64 o = __shfl_xor_sync(0xFFFFFFFFu, v, j);
                bool keep_max = ((tid & j) == 0) == ((tid & k) == 0);
                bool vbig = v > o;
                v = (keep_max == vbig) ? v : o;
            }
            if (k < SEL_N) {
                bufs[cur][tid] = v;
                __syncthreads();
            }
        }
        mykey = v;
    } else {
        u64* sbuf = skey;
        const int n = CANDCAP;
        __syncthreads();
        for (int k = 2; k <= n; k <<= 1) {
            for (int j = k >> 1; j > 0; j >>= 1) {
                for (int q = 0; q < n; q += SORT_T) {
                    int i = tid + q;
                    int ixj = i ^ j;
                    if (ixj > i) {
                        u64 a = sbuf[i], b = sbuf[ixj];
                        if (((i & k) == 0) ? (a < b) : (a > b)) {
                            sbuf[i] = b; sbuf[ixj] = a;
                        }
                    }
                }
                __syncthreads();
            }
        }
        mykey = sbuf[tid];
    }

    if (tid < TOPK) {
        u64 key = mykey;
        float4 b; float sc, ar; int idx;
        if ((key >> 32) != 0ull) {
            idx = (int)(0xFFFFFFFFu - (u32)(key & 0xFFFFFFFFull));
            sc  = __uint_as_float((u32)(key >> 32));
            float x = p[idx * PRED_C + 0];
            float y = p[idx * PRED_C + 1];
            float w = p[idx * PRED_C + 2];
            float h = p[idx * PRED_C + 3];
            float hw = __fmul_rn(w, 0.5f);
            float hh = __fmul_rn(h, 0.5f);
            b = make_float4(__fsub_rn(x, hw), __fsub_rn(y, hh),
                            __fadd_rn(x, hw), __fadd_rn(y, hh));
            ar = __fmul_rn(__fsub_rn(b.z, b.x), __fsub_rn(b.w, b.y));
        } else {
            idx = -1; sc = -1.0f; ar = 0.0f;
            b = make_float4(0.f, 0.f, 0.f, 0.f);
        }
        g_box  [img * 1024 + tid] = b;
        g_score[img * 1024 + tid] = sc;
        g_area [img * 1024 + tid] = ar;
        g_idx  [img * 1024 + tid] = idx;
    }
}

// ============================================================
// 3) mask: transposed store (R16 verbatim + img_base)
// ============================================================
__global__ __launch_bounds__(MASK_T)
void k_mask(int img_base)
{
    __shared__ float4 sbox[TOPK];
    __shared__ float  sarea[TOPK];

    const int img  = img_base + blockIdx.x;
    const int tid  = threadIdx.x;
    const int lane = tid & 31;
    const int gw   = blockIdx.y * (MASK_T / 32) + (tid >> 5);

    for (int i = tid; i < TOPK; i += MASK_T) {
        sbox[i]  = g_box [img * 1024 + i];
        sarea[i] = g_area[img * 1024 + i];
    }
    __syncthreads();

    u32* gmT = g_maskT + (size_t)img * 32 * 1024;

    int u    = (int)(((long long)gw * TASKS) / NWARPS_M);
    int uend = (int)(((long long)(gw + 1) * TASKS) / NWARPS_M);

    int w = 0, acc = 0;
    while (true) {
        int cw = 32 * w + 32; if (cw > TOPK) cw = TOPK;
        if (acc + cw > u) break;
        acc += cw; w++;
    }
    int i  = u - acc;
    int cw = 32 * w + 32; if (cw > TOPK) cw = TOPK;

    int j = w * 32 + lane;
    bool jv = (j < TOPK);
    float4 bj = sbox[jv ? j : 0];
    float  aj = sarea[jv ? j : 0];

    for (; u < uend; ++u) {
        if (i == cw) {
            w++; i = 0;
            cw = 32 * w + 32; if (cw > TOPK) cw = TOPK;
            j = w * 32 + lane;
            jv = (j < TOPK);
            bj = sbox[jv ? j : 0];
            aj = sarea[jv ? j : 0];
        }
        float4 bi = sbox[i];
        float  ai = sarea[i];
        float lx = fmaxf(bi.x, bj.x);
        float ly = fmaxf(bi.y, bj.y);
        float rx = fminf(bi.z, bj.z);
        float ry = fminf(bi.w, bj.w);
        float iw = fmaxf(__fsub_rn(rx, lx), 0.0f);
        float ih = fmaxf(__fsub_rn(ry, ly), 0.0f);
        float inter = __fmul_rn(iw, ih);
        bool sup = false;
        if (j > i && jv && inter > 0.0f) {
            float denom = __fadd_rn(__fsub_rn(__fadd_rn(ai, aj), inter), 1e-7f);
            sup = (__fdiv_rn(inter, denom) > IOU_T);
        }
        u32 word = __ballot_sync(0xFFFFFFFFu, sup);
        if (lane == 0) gmT[w * 1024 + i] = word;
        i++;
    }
}

// ============================================================
// 4) sweep: Jacobi fixed point (R16 verbatim + img_base)
// ============================================================
__global__ __launch_bounds__(SWEEP_T, 1)
void k_sweep(const float* __restrict__ pred,
             float* __restrict__ out,
             float* __restrict__ keep_out,
             int img_base)
{
    extern __shared__ unsigned char sraw[];
    u32* smaskT = (u32*)sraw;
    u32* svalid = smaskT + 32 * 1024;
    u32* skeepv = svalid + 32;
    int* schg   = (int*)(skeepv + 32);

    const int img  = img_base + blockIdx.x;
    const int tid  = threadIdx.x;
    const int warp = tid >> 5, lane = tid & 31;

    {
        const uint4* src = (const uint4*)(g_maskT + (size_t)img * 32 * 1024);
        uint4* dst = (uint4*)smaskT;
        #pragma unroll
        for (int r = 0; r < 8; r++)
            dst[tid + r * SWEEP_T] = src[tid + r * SWEEP_T];
    }

    {
        float sc = (tid < TOPK) ? g_score[img * 1024 + tid] : -1.0f;
        u32 vb = __ballot_sync(0xFFFFFFFFu, sc > CONF_T);
        if (lane == 0) { svalid[warp] = vb; skeepv[warp] = vb; }
        if (tid < 2) schg[tid] = 0;
    }
    __syncthreads();

    for (int it = 0; it < 1100; ++it) {
        int cur = it & 1;
        u32 partial = 0;
        for (int q = 0; q <= warp; q++) {
            u32 kw = skeepv[q];
            u32 bm = 0u - ((kw >> lane) & 1u);
            partial |= smaskT[warp * 1024 + q * 32 + lane] & bm;
        }
        u32 sup = __reduce_or_sync(0xFFFFFFFFu, partial);
        u32 nk  = svalid[warp] & ~sup;
        u32 old = skeepv[warp];
        __syncthreads();
        if (lane == 0) {
            skeepv[warp] = nk;
            if (nk != old) schg[cur] = 1;
        }
        if (tid == 0) schg[cur ^ 1] = 0;
        __syncthreads();
        if (!schg[cur]) break;
    }

    const float* p = pred + (size_t)img * NPRED * PRED_C;
    if (tid < TOPK) {
        bool kp = (skeepv[tid >> 5] >> (tid & 31)) & 1u;
        float o0=0.f,o1=0.f,o2=0.f,o3=0.f,o4=0.f,o6=0.f,o7=0.f,o8=0.f;
        if (kp) {
            float4 b = g_box[img * 1024 + tid];
            o0 = b.x; o1 = b.y; o2 = b.z; o3 = b.w;
            o4 = g_score[img * 1024 + tid];
            int idx = g_idx[img * 1024 + tid];
            o6 = p[idx * PRED_C + 6];
            o7 = p[idx * PRED_C + 7];
            o8 = p[idx * PRED_C + 8];
        }
        float* orow = out + ((size_t)img * TOPK + tid) * PRED_C;
        orow[0]=o0; orow[1]=o1; orow[2]=o2; orow[3]=o3;
        orow[4]=o4; orow[5]=0.0f;
        orow[6]=o6; orow[7]=o7; orow[8]=o8;
        keep_out[(size_t)img * TOPK + tid] = kp ? 1.0f : 0.0f;
    }
}

// ============================================================
// launcher: 4 parallel per-group chains via forked streams
// ============================================================
static cudaStream_t s_streams[NGROUPS];   // [0] unused (legacy stream)
static cudaEvent_t  s_evRoot;
static cudaEvent_t  s_evDone[NGROUPS];
static bool         s_init = false;

extern "C" void kernel_launch(void* const* d_in, const int* in_sizes, int n_in,
                              void* d_out, int out_size)
{
    const float* pred = (const float*)d_in[0];
    int B = in_sizes[0] / (NPRED * PRED_C);

    float* out  = (float*)d_out;
    float* keep = out + (size_t)B * TOPK * PRED_C;

    size_t smemSort  = (size_t)CANDCAP * 8 + (size_t)SEL_N * 8 * 2 +
                       1024 * 4 + 64 * 4 + 80 * 4;
    size_t smemSweep = (size_t)32 * 1024 * 4 + 64 * 4 + 2 * 4 + 64;

    if (!s_init) {
        cudaFuncSetAttribute(k_sort,  cudaFuncAttributeMaxDynamicSharedMemorySize,
                             (int)smemSort);
        cudaFuncSetAttribute(k_sweep, cudaFuncAttributeMaxDynamicSharedMemorySize,
                             (int)smemSweep);
        for (int g = 1; g < NGROUPS; g++)
            cudaStreamCreateWithFlags(&s_streams[g], cudaStreamNonBlocking);
        cudaEventCreateWithFlags(&s_evRoot, cudaEventDisableTiming);
        for (int g = 1; g < NGROUPS; g++)
            cudaEventCreateWithFlags(&s_evDone[g], cudaEventDisableTiming);
        s_init = true;
    }

    if (B % NGROUPS != 0) {
        // fallback: single-stream full batch
        k_filter<<<dim3(B, NSLICE), FILT_T>>>(pred, 0);
        k_sort<<<B, SORT_T, smemSort>>>(pred, 0);
        k_mask<<<dim3(B, MSLICES), MASK_T>>>(0);
        k_sweep<<<B, SWEEP_T, smemSweep>>>(pred, out, keep, 0);
        return;
    }

    const int Bg = B / NGROUPS;

    // fork
    cudaEventRecord(s_evRoot, 0);
    for (int g = 1; g < NGROUPS; g++)
        cudaStreamWaitEvent(s_streams[g], s_evRoot, 0);

    for (int g = 0; g < NGROUPS; g++) {
        cudaStream_t st = (g == 0) ? (cudaStream_t)0 : s_streams[g];
        int img0 = g * Bg;
        k_filter<<<dim3(Bg, NSLICE), FILT_T, 0, st>>>(pred, img0);
        k_sort<<<Bg, SORT_T, smemSort, st>>>(pred, img0);
        k_mask<<<dim3(Bg, MSLICES), MASK_T, 0, st>>>(img0);
        k_sweep<<<Bg, SWEEP_T, smemSweep, st>>>(pred, out, keep, img0);
    }

    // join
    for (int g = 1; g < NGROUPS; g++) {
        cudaEventRecord(s_evDone[g], s_streams[g]);
        cudaStreamWaitEvent((cudaStream_t)0, s_evDone[g], 0);
    }
}